// round 4
// baseline (speedup 1.0000x reference)
#include <cuda_runtime.h>
#include <cuda_bf16.h>

#define B   256
#define T   1024
#define H   128
#define I   19
#define BT  (B*T)            // 262144
#define NEL (BT*H)           // 33554432

// Scratch (device globals: allocation-free per harness rules)
__device__ float g_pre0[NEL];   // layer-0 pre-activations
__device__ float g_pre1[NEL];   // layer-1 pre-activations (produced by fused scan0)

typedef unsigned long long u64;

__device__ __forceinline__ u64 fma2(u64 a, u64 b, u64 c) {
    u64 d;
    asm("fma.rn.f32x2 %0, %1, %2, %3;" : "=l"(d) : "l"(a), "l"(b), "l"(c));
    return d;
}
__device__ __forceinline__ u64 add2(u64 a, u64 b) {
    u64 d;
    asm("add.rn.f32x2 %0, %1, %2;" : "=l"(d) : "l"(a), "l"(b));
    return d;
}
__device__ __forceinline__ float red2(u64 a) {
    float x, y;
    asm("mov.b64 {%0, %1}, %2;" : "=f"(x), "=f"(y) : "l"(a));
    return x + y;
}
__device__ __forceinline__ float fast_tanh(float x) {
    float r;
    asm("tanh.approx.f32 %0, %1;" : "=f"(r) : "f"(x));
    return r;
}

// ---------------------------------------------------------------------------
// Kernel 1: pre0[bt, j] = x[bt, :19] . W_ih0[j, :19] + b_ih0[j] + b_hh0[j]
// ---------------------------------------------------------------------------
__global__ void pre0_kernel(const float* __restrict__ x,
                            const float* __restrict__ W,
                            const float* __restrict__ bi,
                            const float* __restrict__ bh) {
    int idx = blockIdx.x * 256 + threadIdx.x;
    int j  = idx & (H - 1);
    int bt = idx >> 7;
    const float* xr = x + bt * I;
    const float* wr = W + j * I;
    float acc = __ldg(bi + j) + __ldg(bh + j);
#pragma unroll
    for (int f = 0; f < I; f++)
        acc = fmaf(__ldg(xr + f), __ldg(wr + f), acc);
    g_pre0[idx] = acc;
}

// ---------------------------------------------------------------------------
// Kernel 2: FUSED layer-0 scan + layer-1 input projection.
// One CTA (128 thr) per batch row; thread j owns unit j, W_hh0 row j in 64
// packed f32x2 registers. Per step the same shared h-vector loads feed BOTH
// the recurrence dot (next h) and the W_ih1 projection dot (pre1 of the
// PREVIOUS timestep's h). h1 never touches global memory; proj kernel gone.
// W_ih1 staged in 64KB dynamic shared as transposed f32x2 pairs WT2[q][j]
// (per-q warp access spans 256B -> conflict-free).
// Manual 2x unroll: static double-buffer pointers + 2 static prefetch regs.
// ---------------------------------------------------------------------------
#define SC0_SMEM (64*128*8 + 2*128*4)

__global__ void __launch_bounds__(128, 2)
scan0_fused(const float* __restrict__ Whh,
            const float* __restrict__ Wih1,
            const float* __restrict__ bi1,
            const float* __restrict__ bh1) {
    extern __shared__ __align__(16) char smem[];
    u64*   WT2 = reinterpret_cast<u64*>(smem);            // [64][128]
    float* hA  = reinterpret_cast<float*>(smem + 64*128*8);
    float* hB  = hA + 128;

    const int j = threadIdx.x;
    const int b = blockIdx.x;
    const float* __restrict__ pre = g_pre0;
    float* __restrict__ p1out = g_pre1;

    // W_hh0 row j in registers.
    u64 wp[64];
    const u64* wrow = reinterpret_cast<const u64*>(Whh + j * H);
#pragma unroll
    for (int i = 0; i < 64; i++) wp[i] = __ldg(wrow + i);

    // Stage W_ih1 transposed pairs: WT2[q][j] = (Wih1[j][2q], Wih1[j][2q+1]).
    const u64* wirow = reinterpret_cast<const u64*>(Wih1 + j * H);
#pragma unroll
    for (int q = 0; q < 64; q++) WT2[q * 128 + j] = __ldg(wirow + q);

    const float bias1 = __ldg(bi1 + j) + __ldg(bh1 + j);
    hA[j] = 0.0f;

    const int base = b * (T * H) + j;
    float pA = __ldg(pre + base);           // pre0 for t (even phase)
    float pB = __ldg(pre + base + H);       // pre0 for t+1 (odd phase)
    __syncthreads();

#pragma unroll 1
    for (int t = 0; t < T; t += 2) {
        // ---- phase A: hin = hA = h(t-1); compute h(t)->hB, pre1(t-1) ----
        {
            const ulonglong2* hp = reinterpret_cast<const ulonglong2*>(hA);
            u64 a0=0,a1=0,a2=0,a3=0,c0=0,c1=0,c2=0,c3=0;
#pragma unroll
            for (int i = 0; i < 16; i++) {
                ulonglong2 q0 = hp[2*i], q1 = hp[2*i+1];
                u64 w0 = WT2[(4*i+0)*128 + j], w1 = WT2[(4*i+1)*128 + j];
                u64 w2 = WT2[(4*i+2)*128 + j], w3 = WT2[(4*i+3)*128 + j];
                a0 = fma2(wp[4*i+0], q0.x, a0); a1 = fma2(wp[4*i+1], q0.y, a1);
                a2 = fma2(wp[4*i+2], q1.x, a2); a3 = fma2(wp[4*i+3], q1.y, a3);
                c0 = fma2(w0, q0.x, c0);        c1 = fma2(w1, q0.y, c1);
                c2 = fma2(w2, q1.x, c2);        c3 = fma2(w3, q1.y, c3);
            }
            float h = fast_tanh(pA + red2(add2(add2(a0,a2), add2(a1,a3))));
            hB[j] = h;
            // pre1 of PREVIOUS step's h; t=0 writes slot 1023 with a dummy,
            // overwritten by the epilogue afterwards (same thread, ordered).
            p1out[base + ((t-1) & (T-1)) * H] =
                bias1 + red2(add2(add2(c0,c2), add2(c1,c3)));
            int tn = (t + 2 < T) ? (t + 2) : (T - 1);
            pA = __ldg(pre + base + tn * H);
            __syncthreads();
        }
        // ---- phase B: hin = hB = h(t); compute h(t+1)->hA, pre1(t) ----
        {
            const ulonglong2* hp = reinterpret_cast<const ulonglong2*>(hB);
            u64 a0=0,a1=0,a2=0,a3=0,c0=0,c1=0,c2=0,c3=0;
#pragma unroll
            for (int i = 0; i < 16; i++) {
                ulonglong2 q0 = hp[2*i], q1 = hp[2*i+1];
                u64 w0 = WT2[(4*i+0)*128 + j], w1 = WT2[(4*i+1)*128 + j];
                u64 w2 = WT2[(4*i+2)*128 + j], w3 = WT2[(4*i+3)*128 + j];
                a0 = fma2(wp[4*i+0], q0.x, a0); a1 = fma2(wp[4*i+1], q0.y, a1);
                a2 = fma2(wp[4*i+2], q1.x, a2); a3 = fma2(wp[4*i+3], q1.y, a3);
                c0 = fma2(w0, q0.x, c0);        c1 = fma2(w1, q0.y, c1);
                c2 = fma2(w2, q1.x, c2);        c3 = fma2(w3, q1.y, c3);
            }
            float h = fast_tanh(pB + red2(add2(add2(a0,a2), add2(a1,a3))));
            hA[j] = h;
            p1out[base + t * H] =
                bias1 + red2(add2(add2(c0,c2), add2(c1,c3)));
            int tn = (t + 3 < T) ? (t + 3) : (T - 1);
            pB = __ldg(pre + base + tn * H);
            __syncthreads();
        }
    }
    // Epilogue: pre1 of h(T-1), which sits in hA.
    {
        const ulonglong2* hp = reinterpret_cast<const ulonglong2*>(hA);
        u64 c0=0,c1=0,c2=0,c3=0;
#pragma unroll
        for (int i = 0; i < 16; i++) {
            ulonglong2 q0 = hp[2*i], q1 = hp[2*i+1];
            c0 = fma2(WT2[(4*i+0)*128 + j], q0.x, c0);
            c1 = fma2(WT2[(4*i+1)*128 + j], q0.y, c1);
            c2 = fma2(WT2[(4*i+2)*128 + j], q1.x, c2);
            c3 = fma2(WT2[(4*i+3)*128 + j], q1.y, c3);
        }
        p1out[base + (T-1) * H] = bias1 + red2(add2(add2(c0,c2), add2(c1,c3)));
    }
}

// ---------------------------------------------------------------------------
// Kernel 3: plain layer-1 scan on g_pre1 -> final output. Manual 2x unroll,
// static double buffers + static prefetch registers.
// ---------------------------------------------------------------------------
__global__ void __launch_bounds__(128, 2)
scan1_kernel(const float* __restrict__ Whh, float* __restrict__ out) {
    __shared__ __align__(16) float hAb[H], hBb[H];
    const int j = threadIdx.x;
    const int b = blockIdx.x;
    const float* __restrict__ pre = g_pre1;

    u64 wp[64];
    const u64* wrow = reinterpret_cast<const u64*>(Whh + j * H);
#pragma unroll
    for (int i = 0; i < 64; i++) wp[i] = __ldg(wrow + i);

    hAb[j] = 0.0f;
    const int base = b * (T * H) + j;
    float pA = __ldg(pre + base);
    float pB = __ldg(pre + base + H);
    __syncthreads();

#pragma unroll 1
    for (int t = 0; t < T; t += 2) {
        {
            const ulonglong2* hp = reinterpret_cast<const ulonglong2*>(hAb);
            u64 a0=0,a1=0,a2=0,a3=0;
#pragma unroll
            for (int i = 0; i < 16; i++) {
                ulonglong2 q0 = hp[2*i], q1 = hp[2*i+1];
                a0 = fma2(wp[4*i+0], q0.x, a0); a1 = fma2(wp[4*i+1], q0.y, a1);
                a2 = fma2(wp[4*i+2], q1.x, a2); a3 = fma2(wp[4*i+3], q1.y, a3);
            }
            float h = fast_tanh(pA + red2(add2(add2(a0,a2), add2(a1,a3))));
            hBb[j] = h;
            out[base + t * H] = h;
            int tn = (t + 2 < T) ? (t + 2) : (T - 1);
            pA = __ldg(pre + base + tn * H);
            __syncthreads();
        }
        {
            const ulonglong2* hp = reinterpret_cast<const ulonglong2*>(hBb);
            u64 a0=0,a1=0,a2=0,a3=0;
#pragma unroll
            for (int i = 0; i < 16; i++) {
                ulonglong2 q0 = hp[2*i], q1 = hp[2*i+1];
                a0 = fma2(wp[4*i+0], q0.x, a0); a1 = fma2(wp[4*i+1], q0.y, a1);
                a2 = fma2(wp[4*i+2], q1.x, a2); a3 = fma2(wp[4*i+3], q1.y, a3);
            }
            float h = fast_tanh(pB + red2(add2(add2(a0,a2), add2(a1,a3))));
            hAb[j] = h;
            out[base + (t+1) * H] = h;
            int tn = (t + 3 < T) ? (t + 3) : (T - 1);
            pB = __ldg(pre + base + tn * H);
            __syncthreads();
        }
    }
}

// ---------------------------------------------------------------------------
extern "C" void kernel_launch(void* const* d_in, const int* in_sizes, int n_in,
                              void* d_out, int out_size) {
    const float* x     = (const float*)d_in[0];
    const float* W_ih0 = (const float*)d_in[1];
    const float* W_hh0 = (const float*)d_in[2];
    const float* b_ih0 = (const float*)d_in[3];
    const float* b_hh0 = (const float*)d_in[4];
    const float* W_ih1 = (const float*)d_in[5];
    const float* W_hh1 = (const float*)d_in[6];
    const float* b_ih1 = (const float*)d_in[7];
    const float* b_hh1 = (const float*)d_in[8];
    float* out = (float*)d_out;

    static bool attr_set = false;
    if (!attr_set) {
        cudaFuncSetAttribute(scan0_fused,
                             cudaFuncAttributeMaxDynamicSharedMemorySize,
                             SC0_SMEM);
        attr_set = true;
    }

    // Layer 0 input projection -> g_pre0
    pre0_kernel<<<NEL / 256, 256>>>(x, W_ih0, b_ih0, b_hh0);
    // Fused layer-0 scan + layer-1 projection -> g_pre1
    scan0_fused<<<B, 128, SC0_SMEM>>>(W_hh0, W_ih1, b_ih1, b_hh1);
    // Layer-1 scan -> out
    scan1_kernel<<<B, 128>>>(W_hh1, out);
}

// round 5
// speedup vs baseline: 1.4584x; 1.4584x over previous
#include <cuda_runtime.h>
#include <cuda_bf16.h>
#include <cstdint>

#define B   256
#define T   1024
#define H   128
#define I   19
#define BT  (B*T)            // 262144
#define NEL (BT*H)           // 33554432

// Scratch (device globals: allocation-free per harness rules)
__device__ float g_pre[NEL];   // pre-activations (layer0, then overwritten with layer1's)
__device__ float g_h1[NEL];    // layer-0 hidden outputs

typedef unsigned long long u64;

__device__ __forceinline__ u64 fma2(u64 a, u64 b, u64 c) {
    u64 d;
    asm("fma.rn.f32x2 %0, %1, %2, %3;" : "=l"(d) : "l"(a), "l"(b), "l"(c));
    return d;
}
__device__ __forceinline__ u64 add2(u64 a, u64 b) {
    u64 d;
    asm("add.rn.f32x2 %0, %1, %2;" : "=l"(d) : "l"(a), "l"(b));
    return d;
}
__device__ __forceinline__ float red2(u64 a) {
    float x, y;
    asm("mov.b64 {%0, %1}, %2;" : "=f"(x), "=f"(y) : "l"(a));
    return x + y;
}
__device__ __forceinline__ float fast_tanh(float x) {
    float r;
    asm("tanh.approx.f32 %0, %1;" : "=f"(r) : "f"(x));
    return r;
}
__device__ __forceinline__ void cp16(uint32_t daddr, const void* gptr) {
    asm volatile("cp.async.ca.shared.global [%0], [%1], 16;\n"
                 :: "r"(daddr), "l"(gptr));
}

// ---------------------------------------------------------------------------
// Kernel 1: pre0[bt, j] = x[bt, :19] . W_ih0[j, :19] + b_ih0[j] + b_hh0[j]
// One block per 64 bt rows. W row j lives in 19 registers of thread j; the
// x tile (64 rows * 19 floats = 4864 contiguous bytes) is staged to shared
// with coalesced float4 loads; compute reads are warp-broadcast LDS.
// ---------------------------------------------------------------------------
#define P0_ROWS 64
#define P0_F4   ((P0_ROWS * I) / 4)   // 304 float4 per tile

__global__ void __launch_bounds__(128)
pre0_kernel(const float* __restrict__ x,
            const float* __restrict__ W,
            const float* __restrict__ bi,
            const float* __restrict__ bh) {
    __shared__ __align__(16) float xs[P0_ROWS * I];
    const int j = threadIdx.x;

    float w[I];
#pragma unroll
    for (int f = 0; f < I; f++) w[f] = __ldg(W + j * I + f);
    const float bias = __ldg(bi + j) + __ldg(bh + j);

    const int rbeg = blockIdx.x * P0_ROWS;
    const float4* src = reinterpret_cast<const float4*>(x + (size_t)rbeg * I);
    float4* dst = reinterpret_cast<float4*>(xs);
    dst[j] = src[j];
    dst[j + 128] = src[j + 128];
    if (j < P0_F4 - 256) dst[j + 256] = src[j + 256];
    __syncthreads();

    float* outp = g_pre + (size_t)rbeg * H + j;
#pragma unroll 4
    for (int r = 0; r < P0_ROWS; r += 4) {
        float a0 = bias, a1 = bias, a2 = bias, a3 = bias;
#pragma unroll
        for (int f = 0; f < I; f++) {
            a0 = fmaf(xs[(r + 0) * I + f], w[f], a0);
            a1 = fmaf(xs[(r + 1) * I + f], w[f], a1);
            a2 = fmaf(xs[(r + 2) * I + f], w[f], a2);
            a3 = fmaf(xs[(r + 3) * I + f], w[f], a3);
        }
        outp[(r + 0) * H] = a0;
        outp[(r + 1) * H] = a1;
        outp[(r + 2) * H] = a2;
        outp[(r + 3) * H] = a3;
    }
}

// ---------------------------------------------------------------------------
// Kernel 2: recurrent scan (plain, round-3 proven structure). One CTA
// (128 thr) per batch row, W_hh row j in 64 packed f32x2 registers, h
// double-buffered in shared, manual 2x unroll with static prefetch regs.
// layer==0: g_pre -> g_h1 ; layer==1: g_pre -> dout.
// ---------------------------------------------------------------------------
__global__ void __launch_bounds__(128, 2)
scan_kernel(int layer, const float* __restrict__ Whh, float* __restrict__ dout) {
    __shared__ __align__(16) float hAb[H], hBb[H];
    const int j = threadIdx.x;
    const int b = blockIdx.x;
    const float* __restrict__ pre = g_pre;
    float* __restrict__ out = (layer == 0) ? g_h1 : dout;

    u64 wp[64];
    const u64* wrow = reinterpret_cast<const u64*>(Whh + j * H);
#pragma unroll
    for (int i = 0; i < 64; i++) wp[i] = __ldg(wrow + i);

    hAb[j] = 0.0f;
    const int base = b * (T * H) + j;
    float pA = __ldg(pre + base);
    float pB = __ldg(pre + base + H);
    __syncthreads();

#pragma unroll 1
    for (int t = 0; t < T; t += 2) {
        {
            const ulonglong2* hp = reinterpret_cast<const ulonglong2*>(hAb);
            u64 a0 = 0, a1 = 0, a2 = 0, a3 = 0;
#pragma unroll
            for (int i = 0; i < 16; i++) {
                ulonglong2 q0 = hp[2 * i], q1 = hp[2 * i + 1];
                a0 = fma2(wp[4 * i + 0], q0.x, a0);
                a1 = fma2(wp[4 * i + 1], q0.y, a1);
                a2 = fma2(wp[4 * i + 2], q1.x, a2);
                a3 = fma2(wp[4 * i + 3], q1.y, a3);
            }
            float h = fast_tanh(pA + red2(add2(add2(a0, a2), add2(a1, a3))));
            hBb[j] = h;
            out[base + t * H] = h;
            int tn = (t + 2 < T) ? (t + 2) : (T - 1);
            pA = __ldg(pre + base + tn * H);
            __syncthreads();
        }
        {
            const ulonglong2* hp = reinterpret_cast<const ulonglong2*>(hBb);
            u64 a0 = 0, a1 = 0, a2 = 0, a3 = 0;
#pragma unroll
            for (int i = 0; i < 16; i++) {
                ulonglong2 q0 = hp[2 * i], q1 = hp[2 * i + 1];
                a0 = fma2(wp[4 * i + 0], q0.x, a0);
                a1 = fma2(wp[4 * i + 1], q0.y, a1);
                a2 = fma2(wp[4 * i + 2], q1.x, a2);
                a3 = fma2(wp[4 * i + 3], q1.y, a3);
            }
            float h = fast_tanh(pB + red2(add2(add2(a0, a2), add2(a1, a3))));
            hAb[j] = h;
            out[base + (t + 1) * H] = h;
            int tn = (t + 3 < T) ? (t + 3) : (T - 1);
            pB = __ldg(pre + base + tn * H);
            __syncthreads();
        }
    }
}

// ---------------------------------------------------------------------------
// Kernel 3: layer-1 input projection with a 4-stage cp.async pipeline.
// pre1[r, j] = h1[r, :] . W_ih1[j, :] + b_ih1[j] + b_hh1[j]
// 8-row (4KB) stages; wait_group<=2 keeps 3 stages in flight so DRAM latency
// is fully covered by ~2 tiles of fma2 work.
// ---------------------------------------------------------------------------
#define PROJ_BLOCKS 512
#define PROJ_ROWS   (BT / PROJ_BLOCKS)   // 512 rows per block
#define PTILE       8
#define NTILES      (PROJ_ROWS / PTILE)  // 64
#define NSTAGE      4
#define STAGE_BYTES (PTILE * H * 4)      // 4096

__global__ void __launch_bounds__(128, 2)
proj_kernel(const float* __restrict__ W,
            const float* __restrict__ bi,
            const float* __restrict__ bh) {
    __shared__ __align__(16) float sh[NSTAGE][PTILE * H];
    const int j = threadIdx.x;
    const uint32_t shbase = (uint32_t)__cvta_generic_to_shared(sh);

    u64 wp[64];
    const u64* wrow = reinterpret_cast<const u64*>(W + j * H);
#pragma unroll
    for (int i = 0; i < 64; i++) wp[i] = __ldg(wrow + i);

    const float bias = __ldg(bi + j) + __ldg(bh + j);
    const int rbeg = blockIdx.x * PROJ_ROWS;

    // Issue stages 0..2
#pragma unroll
    for (int s = 0; s < 3; s++) {
        const float4* src = reinterpret_cast<const float4*>(
            g_h1 + (size_t)(rbeg + s * PTILE) * H);
        uint32_t d = shbase + s * STAGE_BYTES + j * 16;
        cp16(d, src + j);
        cp16(d + 2048, src + j + 128);
        asm volatile("cp.async.commit_group;\n");
    }

#pragma unroll 1
    for (int ti = 0; ti < NTILES; ti++) {
        asm volatile("cp.async.wait_group 2;\n");
        __syncthreads();

        if (ti + 3 < NTILES) {
            int s = (ti + 3) & (NSTAGE - 1);
            const float4* src = reinterpret_cast<const float4*>(
                g_h1 + (size_t)(rbeg + (ti + 3) * PTILE) * H);
            uint32_t d = shbase + s * STAGE_BYTES + j * 16;
            cp16(d, src + j);
            cp16(d + 2048, src + j + 128);
            asm volatile("cp.async.commit_group;\n");
        }

        const float* stage = sh[ti & (NSTAGE - 1)];
        float* outp = g_pre + (size_t)(rbeg + ti * PTILE) * H + j;
#pragma unroll
        for (int i = 0; i < PTILE; i++) {
            const ulonglong2* hp = reinterpret_cast<const ulonglong2*>(stage + i * H);
            u64 a0 = 0, a1 = 0, a2 = 0, a3 = 0;
#pragma unroll
            for (int q = 0; q < 16; q++) {
                ulonglong2 x0 = hp[2 * q], x1 = hp[2 * q + 1];
                a0 = fma2(wp[4 * q + 0], x0.x, a0);
                a1 = fma2(wp[4 * q + 1], x0.y, a1);
                a2 = fma2(wp[4 * q + 2], x1.x, a2);
                a3 = fma2(wp[4 * q + 3], x1.y, a3);
            }
            outp[i * H] = bias + red2(add2(add2(a0, a2), add2(a1, a3)));
        }
        __syncthreads();
    }
}

// ---------------------------------------------------------------------------
extern "C" void kernel_launch(void* const* d_in, const int* in_sizes, int n_in,
                              void* d_out, int out_size) {
    const float* x     = (const float*)d_in[0];
    const float* W_ih0 = (const float*)d_in[1];
    const float* W_hh0 = (const float*)d_in[2];
    const float* b_ih0 = (const float*)d_in[3];
    const float* b_hh0 = (const float*)d_in[4];
    const float* W_ih1 = (const float*)d_in[5];
    const float* W_hh1 = (const float*)d_in[6];
    const float* b_ih1 = (const float*)d_in[7];
    const float* b_hh1 = (const float*)d_in[8];
    float* out = (float*)d_out;

    // Layer 0 input projection -> g_pre
    pre0_kernel<<<BT / P0_ROWS, 128>>>(x, W_ih0, b_ih0, b_hh0);
    // Layer 0 scan: g_pre -> g_h1
    scan_kernel<<<B, 128>>>(0, W_hh0, out);
    // Layer 1 input projection: g_h1 -> g_pre
    proj_kernel<<<PROJ_BLOCKS, 128>>>(W_ih1, b_ih1, b_hh1);
    // Layer 1 scan: g_pre -> out
    scan_kernel<<<B, 128>>>(1, W_hh1, out);
}